// round 10
// baseline (speedup 1.0000x reference)
#include <cuda_runtime.h>

// ---------------------------------------------------------------------------
// GATv2 block — algebraically reduced; edge GEMM on tensor cores (tf32 mma).
//
// Identities:
//   Sum_e alpha_e = 1 per destination node with >=1 incoming edge; agg gathers
//   nodes[R] (constant within a segment):
//     agg[n] = flag[n] * (x[n]@W_n + b_n)
//   x_new = relu( flag * (x@W_c + b_c) + G2[batch] )     (exact fp32)
//   e_new = relu( P[L] + edge_attr @ W_e[128:192] )       (tf32 mma + fp32 P)
//       P  = x@W_e[0:128] + b_e                           (exact fp32)
//   g_new = relu( [glob, segment_mean(x_new)] @ W_g + b_g )
// W_le, b_le, a are dead w.r.t. all outputs.
//
// Edge kernel: 128 edges x 128 cols per block, 128 threads (4 warps, m32
// per warp). A staged once -> fragments hoisted to regs -> same smem reused
// for B (pre-packed in fragment order by precompute). B LDS.64 shared by two
// m16 tiles. No syncs in mainloop.
// R10 fix: phase-2 B load source stride 64 f4/row (was 32 — scrambled tile).
// ---------------------------------------------------------------------------

#define MAX_N 50000

__device__ __align__(16) float d_P[MAX_N * 128];   // x @ W_e_top + b_e
__device__ __align__(16) float d_Wc[128 * 128];    // W_n @ W_n2_top
__device__ __align__(16) float d_bc[128];          // b_n @ W_n2_top
__device__ __align__(16) float d_G2[64 * 128];     // glob @ W_n2_bot + b_n2
__device__ __align__(16) float2 d_Webp[32 * 128];  // tf32 W_e[128:192] packed
                                                   // [p=4s+qc][n] = {W[8s+qc][n], W[8s+qc+4][n]}
__device__ int d_flags[MAX_N];

__device__ __forceinline__ int clampi(int v, int lo, int hi) {
    return v < lo ? lo : (v > hi ? hi : v);
}

__device__ __forceinline__ float to_tf32(float x) {
    float r;
    asm("cvt.rna.tf32.f32 %0, %1;" : "=f"(r) : "f"(x));
    return r;
}

// ---------------------------------------------------------------------------
__global__ void flags_zero_kernel(int n) {
    int i = blockIdx.x * blockDim.x + threadIdx.x;
    if (i < n) d_flags[i] = 0;
}

__global__ void flags_set_kernel(const int* __restrict__ eidx, int E, int N) {
    int e = blockIdx.x * blockDim.x + threadIdx.x;
    if (e < E) {
        int r = eidx[E + e];  // edge_index[1][e] (destination)
        if ((unsigned)r < (unsigned)N) d_flags[r] = 1;
    }
}

// grid = 128 (W_c) + 1 (b_c) + B (G2) + 32 (Webp pack rows); 128 threads
__global__ void precompute_kernel(const float* __restrict__ W_n,
                                  const float* __restrict__ b_n,
                                  const float* __restrict__ W_n2,
                                  const float* __restrict__ b_n2,
                                  const float* __restrict__ glob,
                                  const float* __restrict__ W_e, int nGraphs) {
    int blk = blockIdx.x;
    int j = threadIdx.x;  // 0..127
    if (blk < 128) {
        __shared__ float wr[128];
        wr[j] = W_n[blk * 128 + j];
        __syncthreads();
        float acc = 0.f;
#pragma unroll 8
        for (int k = 0; k < 128; ++k) acc = fmaf(wr[k], W_n2[k * 128 + j], acc);
        d_Wc[blk * 128 + j] = acc;
    } else if (blk == 128) {
        float acc = 0.f;
        for (int k = 0; k < 128; ++k) acc = fmaf(b_n[k], W_n2[k * 128 + j], acc);
        d_bc[j] = acc;
    } else if (blk < 129 + nGraphs) {
        int b = blk - 129;
        float acc = b_n2[j];
        for (int k = 0; k < 64; ++k)
            acc = fmaf(glob[b * 64 + k], W_n2[(128 + k) * 128 + j], acc);
        d_G2[b * 128 + j] = acc;
    } else {
        int p = blk - (129 + nGraphs);            // 0..31
        int k = (p >> 2) * 8 + (p & 3);           // s*8 + qc
        float v0 = to_tf32(W_e[(size_t)(128 + k) * 128 + j]);
        float v1 = to_tf32(W_e[(size_t)(128 + k + 4) * 128 + j]);
        d_Webp[p * 128 + j] = make_float2(v0, v1);
    }
}

// ---------------------------------------------------------------------------
// Node kernel (exact fp32): per 64-node tile, (64x128)@(128x256) GEMM.
//   cols 0..127   -> P   -> d_P
//   cols 128..255 -> x_new epilogue (flag, +b_c, +G2[batch], relu)
__global__ __launch_bounds__(256) void node_kernel(
    const float* __restrict__ x, const float* __restrict__ W_e,
    const float* __restrict__ b_e, const int* __restrict__ batch,
    float* __restrict__ xnew, int nNodes, int nGraphs)
{
    __shared__ __align__(16) float xs[64 * 128];   // 32 KB
    const int tid = threadIdx.x;
    const int n0 = blockIdx.x * 64;

    const float4* x4 = reinterpret_cast<const float4*>(x);
    float4* xs4w = reinterpret_cast<float4*>(xs);
    for (int idx = tid; idx < 64 * 32; idx += 256) {
        int node = idx >> 5, kk = idx & 31;
        int gn = n0 + node;
        xs4w[idx] = (gn < nNodes) ? x4[(size_t)gn * 32 + kk]
                                  : make_float4(0.f, 0.f, 0.f, 0.f);
    }
    __syncthreads();

    const int r = tid >> 6;
    const int c = tid & 63;

    const float4* wp = (c < 32)
        ? reinterpret_cast<const float4*>(W_e) + c
        : reinterpret_cast<const float4*>(d_Wc) + (c - 32);

    float acc[16][4];
#pragma unroll
    for (int i = 0; i < 16; ++i) {
        acc[i][0] = 0.f; acc[i][1] = 0.f; acc[i][2] = 0.f; acc[i][3] = 0.f;
    }

    const float4* xs4 = reinterpret_cast<const float4*>(xs);  // [64][32]

#pragma unroll 4
    for (int k4 = 0; k4 < 32; ++k4) {
        float4 w0 = wp[(k4 * 4 + 0) * 32];
        float4 w1 = wp[(k4 * 4 + 1) * 32];
        float4 w2 = wp[(k4 * 4 + 2) * 32];
        float4 w3 = wp[(k4 * 4 + 3) * 32];
#pragma unroll
        for (int i = 0; i < 16; ++i) {
            float4 xv = xs4[(r * 16 + i) * 32 + k4];
            acc[i][0] = fmaf(xv.x, w0.x, acc[i][0]);
            acc[i][1] = fmaf(xv.x, w0.y, acc[i][1]);
            acc[i][2] = fmaf(xv.x, w0.z, acc[i][2]);
            acc[i][3] = fmaf(xv.x, w0.w, acc[i][3]);
            acc[i][0] = fmaf(xv.y, w1.x, acc[i][0]);
            acc[i][1] = fmaf(xv.y, w1.y, acc[i][1]);
            acc[i][2] = fmaf(xv.y, w1.z, acc[i][2]);
            acc[i][3] = fmaf(xv.y, w1.w, acc[i][3]);
            acc[i][0] = fmaf(xv.z, w2.x, acc[i][0]);
            acc[i][1] = fmaf(xv.z, w2.y, acc[i][1]);
            acc[i][2] = fmaf(xv.z, w2.z, acc[i][2]);
            acc[i][3] = fmaf(xv.z, w2.w, acc[i][3]);
            acc[i][0] = fmaf(xv.w, w3.x, acc[i][0]);
            acc[i][1] = fmaf(xv.w, w3.y, acc[i][1]);
            acc[i][2] = fmaf(xv.w, w3.z, acc[i][2]);
            acc[i][3] = fmaf(xv.w, w3.w, acc[i][3]);
        }
    }

    if (c < 32) {
        const float4 bev = reinterpret_cast<const float4*>(b_e)[c];
        float4* P4 = reinterpret_cast<float4*>(d_P);
#pragma unroll
        for (int i = 0; i < 16; ++i) {
            int gn = n0 + r * 16 + i;
            if (gn < nNodes) {
                P4[(size_t)gn * 32 + c] =
                    make_float4(acc[i][0] + bev.x, acc[i][1] + bev.y,
                                acc[i][2] + bev.z, acc[i][3] + bev.w);
            }
        }
    } else {
        const int cc = c - 32;
        const float4 bcv = reinterpret_cast<const float4*>(d_bc)[cc];
        const float4* G24 = reinterpret_cast<const float4*>(d_G2);
        float4* out4 = reinterpret_cast<float4*>(xnew);
#pragma unroll
        for (int i = 0; i < 16; ++i) {
            int gn = n0 + r * 16 + i;
            if (gn < nNodes) {
                int fl = d_flags[gn];
                int b = clampi(batch[gn], 0, nGraphs - 1);
                float4 g2 = G24[b * 32 + cc];
                float4 v;
                v.x = (fl ? acc[i][0] + bcv.x : 0.f) + g2.x;
                v.y = (fl ? acc[i][1] + bcv.y : 0.f) + g2.y;
                v.z = (fl ? acc[i][2] + bcv.z : 0.f) + g2.z;
                v.w = (fl ? acc[i][3] + bcv.w : 0.f) + g2.w;
                v.x = fmaxf(v.x, 0.f); v.y = fmaxf(v.y, 0.f);
                v.z = fmaxf(v.z, 0.f); v.w = fmaxf(v.w, 0.f);
                out4[(size_t)gn * 32 + cc] = v;
            }
        }
    }
}

// ---------------------------------------------------------------------------
// Edge kernel (tf32 mma): e_new = relu(P[L] + edge_attr @ W_eb).
// Block = 128 edges x 128 cols, 128 threads (4 warps, each m=32 rows).
// Phase 1: stage A (stride 68, conflict-free) -> hoist fragments to regs.
// Phase 2: reuse smem for packed B (stride 132 f2), loaded once for all
//          128 cols; mainloop has no syncs.
// h-loop splits accumulators (64 regs per pass) to bound register count.
__global__ __launch_bounds__(128) void edge_kernel(
    const float* __restrict__ edge_attr, const int* __restrict__ eidx,
    float* __restrict__ enew, int E, int nNodes)
{
    __shared__ __align__(16) float sbuf[128 * 68];   // 34816 B, A then B
    __shared__ int Ls[128];

    const int tid = threadIdx.x;
    const int e0 = blockIdx.x * 128;

    {
        int ge = e0 + tid;
        Ls[tid] = (ge < E) ? clampi(eidx[ge], 0, nNodes - 1) : 0;
    }

    // --- Phase 1a: stage A tile (128 edges x 64 k), stride 68 ---
    const float4* ea4 = reinterpret_cast<const float4*>(edge_attr);
#pragma unroll
    for (int it = 0; it < 16; ++it) {
        int idx = tid + it * 128;            // 0..2047
        int e = idx >> 4, kk = idx & 15;
        int ge = e0 + e;
        float4 v = (ge < E) ? ea4[(size_t)ge * 16 + kk]
                            : make_float4(0.f, 0.f, 0.f, 0.f);
        *reinterpret_cast<float4*>(sbuf + e * 68 + kk * 4) = v;
    }
    __syncthreads();

    const int warp = tid >> 5;
    const int lane = tid & 31;
    const int qr = lane >> 2;     // 0..7
    const int qc = lane & 3;      // 0..3

    // --- Phase 1b: hoist A fragments (raw fp32 -> HW tf32 truncation) ---
    float a[2][8][4];
#pragma unroll
    for (int mt = 0; mt < 2; ++mt) {
        const float* r0 = sbuf + (warp * 32 + mt * 16 + qr) * 68;
        const float* r1 = r0 + 8 * 68;
#pragma unroll
        for (int s = 0; s < 8; ++s) {
            a[mt][s][0] = r0[s * 8 + qc];
            a[mt][s][1] = r1[s * 8 + qc];
            a[mt][s][2] = r0[s * 8 + qc + 4];
            a[mt][s][3] = r1[s * 8 + qc + 4];
        }
    }
    __syncthreads();

    // --- Phase 2: load packed B into same smem, stride 132 (f2 units) ---
    // d_Webp rows are 128 f2 = 64 f4 wide (source stride 64, NOT 32).
    float2* Bs2 = reinterpret_cast<float2*>(sbuf);
    const float4* Wp4 = reinterpret_cast<const float4*>(d_Webp);
#pragma unroll
    for (int it = 0; it < 16; ++it) {
        int t = tid + it * 128;              // 0..2047
        int row = t >> 6, cc = t & 63;       // row 0..31, cc 0..63 (f4 units)
        reinterpret_cast<float4*>(Bs2 + row * 132)[cc] = Wp4[row * 64 + cc];
    }
    __syncthreads();

    const float2* P2 = reinterpret_cast<const float2*>(d_P);
    float2* out2 = reinterpret_cast<float2*>(enew);

#pragma unroll
    for (int h = 0; h < 2; ++h) {
        float c[2][8][4];
#pragma unroll
        for (int mt = 0; mt < 2; ++mt)
#pragma unroll
            for (int j = 0; j < 8; ++j) {
                c[mt][j][0] = 0.f; c[mt][j][1] = 0.f;
                c[mt][j][2] = 0.f; c[mt][j][3] = 0.f;
            }

#pragma unroll
        for (int s = 0; s < 8; ++s) {
            const float2* bp = Bs2 + (s * 4 + qc) * 132 + h * 64 + qr;
#pragma unroll
            for (int j = 0; j < 8; ++j) {
                float2 b = bp[8 * j];
#pragma unroll
                for (int mt = 0; mt < 2; ++mt) {
                    asm volatile(
                        "mma.sync.aligned.m16n8k8.row.col.f32.tf32.tf32.f32 "
                        "{%0,%1,%2,%3}, {%4,%5,%6,%7}, {%8,%9}, {%0,%1,%2,%3};"
                        : "+f"(c[mt][j][0]), "+f"(c[mt][j][1]),
                          "+f"(c[mt][j][2]), "+f"(c[mt][j][3])
                        : "r"(__float_as_uint(a[mt][s][0])),
                          "r"(__float_as_uint(a[mt][s][1])),
                          "r"(__float_as_uint(a[mt][s][2])),
                          "r"(__float_as_uint(a[mt][s][3])),
                          "r"(__float_as_uint(b.x)),
                          "r"(__float_as_uint(b.y)));
                }
            }
        }

        // Epilogue: + P[L], relu, store (cols [64h, 64h+64))
#pragma unroll
        for (int mt = 0; mt < 2; ++mt) {
#pragma unroll
            for (int half = 0; half < 2; ++half) {
                int eloc = warp * 32 + mt * 16 + qr + half * 8;
                int ge = e0 + eloc;
                if (ge < E) {
                    int L = Ls[eloc];
                    const float2* prow = P2 + (size_t)L * 64;
                    float2* orow = out2 + (size_t)ge * 64;
#pragma unroll
                    for (int j = 0; j < 8; ++j) {
                        int ci = h * 32 + 4 * j + qc;   // f2 index (col/2)
                        float2 p = prow[ci];
                        float2 v;
                        v.x = fmaxf(c[mt][j][half * 2 + 0] + p.x, 0.f);
                        v.y = fmaxf(c[mt][j][half * 2 + 1] + p.y, 0.f);
                        orow[ci] = v;
                    }
                }
            }
        }
    }
}

// ---------------------------------------------------------------------------
// Global kernel: one block (128 thr) per graph; batch sorted -> binary search.
__global__ void global_kernel(const float* __restrict__ xnew,
                              const int* __restrict__ batch,
                              const float* __restrict__ glob,
                              const float* __restrict__ W_g,
                              const float* __restrict__ b_g,
                              float* __restrict__ gout, int nNodes)
{
    const int b = blockIdx.x;
    const int tid = threadIdx.x;  // 128 threads

    int lo = 0, hi = nNodes;
    while (lo < hi) { int mid = (lo + hi) >> 1; if (batch[mid] < b) lo = mid + 1; else hi = mid; }
    int s = lo;
    lo = s; hi = nNodes;
    while (lo < hi) { int mid = (lo + hi) >> 1; if (batch[mid] < b + 1) lo = mid + 1; else hi = mid; }
    int e2 = lo;

    float sum = 0.f;
    for (int row = s; row < e2; ++row) sum += xnew[(size_t)row * 128 + tid];

    __shared__ float mean_s[128];
    __shared__ float glob_s[64];
    float cnt = fmaxf((float)(e2 - s), 1.0f);
    mean_s[tid] = sum / cnt;
    if (tid < 64) glob_s[tid] = glob[b * 64 + tid];
    __syncthreads();

    if (tid < 64) {
        float acc = b_g[tid];
        for (int k = 0; k < 64; ++k)  acc = fmaf(glob_s[k], W_g[k * 64 + tid], acc);
        for (int k = 0; k < 128; ++k) acc = fmaf(mean_s[k], W_g[(64 + k) * 64 + tid], acc);
        gout[b * 64 + tid] = fmaxf(acc, 0.f);
    }
}

// ---------------------------------------------------------------------------
extern "C" void kernel_launch(void* const* d_in, const int* in_sizes, int n_in,
                              void* d_out, int out_size) {
    const float* x         = (const float*)d_in[0];
    const int*   eidx      = (const int*)d_in[1];
    const float* edge_attr = (const float*)d_in[2];
    const float* glob      = (const float*)d_in[3];
    const int*   batch     = (const int*)d_in[4];
    const float* W_e       = (const float*)d_in[5];
    const float* b_e       = (const float*)d_in[6];
    // d_in[7] = W_le, d_in[8] = b_le -- dead
    const float* W_n       = (const float*)d_in[9];
    const float* b_n       = (const float*)d_in[10];
    const float* W_n2      = (const float*)d_in[11];
    const float* b_n2      = (const float*)d_in[12];
    const float* W_g       = (const float*)d_in[13];
    const float* b_g       = (const float*)d_in[14];
    // d_in[15] = a -- dead

    const int N = in_sizes[0] / 128;
    const int E = in_sizes[1] / 2;
    const int B = in_sizes[3] / 64;

    float* xnew = (float*)d_out;               // [N,128]
    float* enew = xnew + (size_t)N * 128;      // [E,128]
    float* gnew = enew + (size_t)E * 128;      // [B,64]

    flags_zero_kernel<<<(N + 255) / 256, 256>>>(N);
    flags_set_kernel<<<(E + 255) / 256, 256>>>(eidx, E, N);
    precompute_kernel<<<129 + B + 32, 128>>>(W_n, b_n, W_n2, b_n2, glob, W_e, B);
    node_kernel<<<(N + 63) / 64, 256>>>(x, W_e, b_e, batch, xnew, N, B);
    edge_kernel<<<(E + 127) / 128, 128>>>(edge_attr, eidx, enew, E, N);
    global_kernel<<<B, 128>>>(xnew, batch, glob, W_g, b_g, gnew, N);
}

// round 11
// speedup vs baseline: 1.2876x; 1.2876x over previous
#include <cuda_runtime.h>

// ---------------------------------------------------------------------------
// GATv2 block — algebraically reduced; edge GEMM on tensor cores (tf32 mma).
//
// Identities:
//   Sum_e alpha_e = 1 per destination node with >=1 incoming edge; agg gathers
//   nodes[R] (constant within a segment):
//     agg[n] = flag[n] * (x[n]@W_n + b_n)
//   x_new = relu( flag * (x@W_c + b_c) + G2[batch] )     (exact fp32)
//   e_new = relu( P[L] + edge_attr @ W_e[128:192] )       (tf32 mma + fp32 P)
//       P  = x@W_e[0:128] + b_e                           (exact fp32)
//   g_new = relu( [glob, segment_mean(x_new)] @ W_g + b_g )
// W_le, b_le, a are dead w.r.t. all outputs.
//
// R11: edge kernel reverted to the R8 version (256 thr, 64 edges x 128 cols,
// per-pass B staging) — the R10 restructure traded occupancy for fewer LDS
// and regressed. Node kernel gains __launch_bounds__(256,2) to lift it from
// 1 to 2 blocks/SM (was 135 regs -> reg-limited, issue 51.7%).
// ---------------------------------------------------------------------------

#define MAX_N 50000

__device__ __align__(16) float d_P[MAX_N * 128];   // x @ W_e_top + b_e
__device__ __align__(16) float d_Wc[128 * 128];    // W_n @ W_n2_top
__device__ __align__(16) float d_bc[128];          // b_n @ W_n2_top
__device__ __align__(16) float d_G2[64 * 128];     // glob @ W_n2_bot + b_n2
__device__ __align__(16) float d_Web[64 * 128];    // tf32(W_e rows 128..191)
__device__ int d_flags[MAX_N];

__device__ __forceinline__ int clampi(int v, int lo, int hi) {
    return v < lo ? lo : (v > hi ? hi : v);
}

__device__ __forceinline__ float to_tf32(float x) {
    float r;
    asm("cvt.rna.tf32.f32 %0, %1;" : "=f"(r) : "f"(x));
    return r;
}

// ---------------------------------------------------------------------------
__global__ void flags_zero_kernel(int n) {
    int i = blockIdx.x * blockDim.x + threadIdx.x;
    if (i < n) d_flags[i] = 0;
}

__global__ void flags_set_kernel(const int* __restrict__ eidx, int E, int N) {
    int e = blockIdx.x * blockDim.x + threadIdx.x;
    if (e < E) {
        int r = eidx[E + e];  // edge_index[1][e] (destination)
        if ((unsigned)r < (unsigned)N) d_flags[r] = 1;
    }
}

// grid = 128 (W_c) + 1 (b_c) + B (G2) + 64 (d_Web rows); 128 threads
__global__ void precompute_kernel(const float* __restrict__ W_n,
                                  const float* __restrict__ b_n,
                                  const float* __restrict__ W_n2,
                                  const float* __restrict__ b_n2,
                                  const float* __restrict__ glob,
                                  const float* __restrict__ W_e, int nGraphs) {
    int blk = blockIdx.x;
    int j = threadIdx.x;  // 0..127
    if (blk < 128) {
        __shared__ float wr[128];
        wr[j] = W_n[blk * 128 + j];
        __syncthreads();
        float acc = 0.f;
#pragma unroll 8
        for (int k = 0; k < 128; ++k) acc = fmaf(wr[k], W_n2[k * 128 + j], acc);
        d_Wc[blk * 128 + j] = acc;
    } else if (blk == 128) {
        float acc = 0.f;
        for (int k = 0; k < 128; ++k) acc = fmaf(b_n[k], W_n2[k * 128 + j], acc);
        d_bc[j] = acc;
    } else if (blk < 129 + nGraphs) {
        int b = blk - 129;
        float acc = b_n2[j];
        for (int k = 0; k < 64; ++k)
            acc = fmaf(glob[b * 64 + k], W_n2[(128 + k) * 128 + j], acc);
        d_G2[b * 128 + j] = acc;
    } else {
        int r = blk - (129 + nGraphs);  // 0..63
        d_Web[r * 128 + j] = to_tf32(W_e[(size_t)(128 + r) * 128 + j]);
    }
}

// ---------------------------------------------------------------------------
// Node kernel (exact fp32): per 64-node tile, (64x128)@(128x256) GEMM.
//   cols 0..127   -> P   -> d_P
//   cols 128..255 -> x_new epilogue (flag, +b_c, +G2[batch], relu)
// __launch_bounds__(256,2): cap regs at 128 so 2 blocks/SM are resident
// (was 135 regs -> 1 block/SM, issue 51.7%, latency-limited).
__global__ __launch_bounds__(256, 2) void node_kernel(
    const float* __restrict__ x, const float* __restrict__ W_e,
    const float* __restrict__ b_e, const int* __restrict__ batch,
    float* __restrict__ xnew, int nNodes, int nGraphs)
{
    __shared__ __align__(16) float xs[64 * 128];   // 32 KB
    const int tid = threadIdx.x;
    const int n0 = blockIdx.x * 64;

    const float4* x4 = reinterpret_cast<const float4*>(x);
    float4* xs4w = reinterpret_cast<float4*>(xs);
    for (int idx = tid; idx < 64 * 32; idx += 256) {
        int node = idx >> 5, kk = idx & 31;
        int gn = n0 + node;
        xs4w[idx] = (gn < nNodes) ? x4[(size_t)gn * 32 + kk]
                                  : make_float4(0.f, 0.f, 0.f, 0.f);
    }
    __syncthreads();

    const int r = tid >> 6;
    const int c = tid & 63;

    const float4* wp = (c < 32)
        ? reinterpret_cast<const float4*>(W_e) + c
        : reinterpret_cast<const float4*>(d_Wc) + (c - 32);

    float acc[16][4];
#pragma unroll
    for (int i = 0; i < 16; ++i) {
        acc[i][0] = 0.f; acc[i][1] = 0.f; acc[i][2] = 0.f; acc[i][3] = 0.f;
    }

    const float4* xs4 = reinterpret_cast<const float4*>(xs);  // [64][32]

#pragma unroll 4
    for (int k4 = 0; k4 < 32; ++k4) {
        float4 w0 = wp[(k4 * 4 + 0) * 32];
        float4 w1 = wp[(k4 * 4 + 1) * 32];
        float4 w2 = wp[(k4 * 4 + 2) * 32];
        float4 w3 = wp[(k4 * 4 + 3) * 32];
#pragma unroll
        for (int i = 0; i < 16; ++i) {
            float4 xv = xs4[(r * 16 + i) * 32 + k4];
            acc[i][0] = fmaf(xv.x, w0.x, acc[i][0]);
            acc[i][1] = fmaf(xv.x, w0.y, acc[i][1]);
            acc[i][2] = fmaf(xv.x, w0.z, acc[i][2]);
            acc[i][3] = fmaf(xv.x, w0.w, acc[i][3]);
            acc[i][0] = fmaf(xv.y, w1.x, acc[i][0]);
            acc[i][1] = fmaf(xv.y, w1.y, acc[i][1]);
            acc[i][2] = fmaf(xv.y, w1.z, acc[i][2]);
            acc[i][3] = fmaf(xv.y, w1.w, acc[i][3]);
            acc[i][0] = fmaf(xv.z, w2.x, acc[i][0]);
            acc[i][1] = fmaf(xv.z, w2.y, acc[i][1]);
            acc[i][2] = fmaf(xv.z, w2.z, acc[i][2]);
            acc[i][3] = fmaf(xv.z, w2.w, acc[i][3]);
            acc[i][0] = fmaf(xv.w, w3.x, acc[i][0]);
            acc[i][1] = fmaf(xv.w, w3.y, acc[i][1]);
            acc[i][2] = fmaf(xv.w, w3.z, acc[i][2]);
            acc[i][3] = fmaf(xv.w, w3.w, acc[i][3]);
        }
    }

    if (c < 32) {
        const float4 bev = reinterpret_cast<const float4*>(b_e)[c];
        float4* P4 = reinterpret_cast<float4*>(d_P);
#pragma unroll
        for (int i = 0; i < 16; ++i) {
            int gn = n0 + r * 16 + i;
            if (gn < nNodes) {
                P4[(size_t)gn * 32 + c] =
                    make_float4(acc[i][0] + bev.x, acc[i][1] + bev.y,
                                acc[i][2] + bev.z, acc[i][3] + bev.w);
            }
        }
    } else {
        const int cc = c - 32;
        const float4 bcv = reinterpret_cast<const float4*>(d_bc)[cc];
        const float4* G24 = reinterpret_cast<const float4*>(d_G2);
        float4* out4 = reinterpret_cast<float4*>(xnew);
#pragma unroll
        for (int i = 0; i < 16; ++i) {
            int gn = n0 + r * 16 + i;
            if (gn < nNodes) {
                int fl = d_flags[gn];
                int b = clampi(batch[gn], 0, nGraphs - 1);
                float4 g2 = G24[b * 32 + cc];
                float4 v;
                v.x = (fl ? acc[i][0] + bcv.x : 0.f) + g2.x;
                v.y = (fl ? acc[i][1] + bcv.y : 0.f) + g2.y;
                v.z = (fl ? acc[i][2] + bcv.z : 0.f) + g2.z;
                v.w = (fl ? acc[i][3] + bcv.w : 0.f) + g2.w;
                v.x = fmaxf(v.x, 0.f); v.y = fmaxf(v.y, 0.f);
                v.z = fmaxf(v.z, 0.f); v.w = fmaxf(v.w, 0.f);
                out4[(size_t)gn * 32 + cc] = v;
            }
        }
    }
}

// ---------------------------------------------------------------------------
// Edge kernel (tf32 mma, R8 version): e_new = relu(P[L] + edge_attr @ W_eb).
// Block = 64 edges x 128 cols, 256 threads (8 warps: 4 in m x 2 in n).
// Two n-passes of 64 cols over a reused B buffer (A loaded once per block).
// A fed to mma as raw fp32 (HW truncation to tf32); B pre-rounded (d_Web).
// smem: A[64][68] + B[64][72] + Ls = 36 KB (conflict-free fragment loads).
__global__ __launch_bounds__(256) void edge_kernel(
    const float* __restrict__ edge_attr, const int* __restrict__ eidx,
    float* __restrict__ enew, int E, int nNodes)
{
    __shared__ __align__(16) float es[64 * 68];   // 17408 B
    __shared__ __align__(16) float Ws[64 * 72];   // 18432 B
    __shared__ int Ls[64];

    const int tid = threadIdx.x;
    const int e0 = blockIdx.x * 64;

    if (tid < 64) {
        int ge = e0 + tid;
        Ls[tid] = (ge < E) ? clampi(eidx[ge], 0, nNodes - 1) : 0;
    }

    // A tile: 64 edges x 64 k, raw fp32, stride 68 (vectorized LDG->STS)
    const float4* ea4 = reinterpret_cast<const float4*>(edge_attr);
#pragma unroll
    for (int it = 0; it < 4; ++it) {
        int idx = tid + it * 256;            // 0..1023
        int e = idx >> 4, kk = idx & 15;
        int ge = e0 + e;
        float4 v = (ge < E) ? ea4[(size_t)ge * 16 + kk]
                            : make_float4(0.f, 0.f, 0.f, 0.f);
        *reinterpret_cast<float4*>(es + e * 68 + kk * 4) = v;
    }

    const int warp = tid >> 5;
    const int lane = tid & 31;
    const int wm = warp & 3;      // m group: rows [16*wm, 16*wm+16)
    const int wn = warp >> 2;     // n group: pass-local cols [32*wn, +32)
    const int qr = lane >> 2;     // 0..7
    const int qc = lane & 3;      // 0..3

    const float* arow0 = es + (wm * 16 + qr) * 68;
    const float* arow1 = arow0 + 8 * 68;
    const float4* Wg4 = reinterpret_cast<const float4*>(d_Web);

    const float2* P2 = reinterpret_cast<const float2*>(d_P);
    float2* out2 = reinterpret_cast<float2*>(enew);

#pragma unroll
    for (int h = 0; h < 2; ++h) {
        // B half: 64 k x 64 n (cols [64h, 64h+64)), pre-rounded tf32, stride 72
#pragma unroll
        for (int it = 0; it < 4; ++it) {
            int idx = tid + it * 256;        // 0..1023
            int k = idx >> 4, kk = idx & 15;
            float4 v = Wg4[k * 32 + h * 16 + kk];
            *reinterpret_cast<float4*>(Ws + k * 72 + kk * 4) = v;
        }
        __syncthreads();

        float c[4][4];
#pragma unroll
        for (int j = 0; j < 4; ++j) {
            c[j][0] = 0.f; c[j][1] = 0.f; c[j][2] = 0.f; c[j][3] = 0.f;
        }

#pragma unroll
        for (int s = 0; s < 8; ++s) {
            const int kb = s * 8;
            float a0 = arow0[kb + qc];
            float a1 = arow1[kb + qc];
            float a2 = arow0[kb + qc + 4];
            float a3 = arow1[kb + qc + 4];
            const float* b0p = Ws + (kb + qc) * 72 + wn * 32 + qr;
            const float* b1p = b0p + 4 * 72;
#pragma unroll
            for (int j = 0; j < 4; ++j) {
                float b0 = b0p[8 * j];
                float b1 = b1p[8 * j];
                asm volatile(
                    "mma.sync.aligned.m16n8k8.row.col.f32.tf32.tf32.f32 "
                    "{%0,%1,%2,%3}, {%4,%5,%6,%7}, {%8,%9}, {%0,%1,%2,%3};"
                    : "+f"(c[j][0]), "+f"(c[j][1]), "+f"(c[j][2]), "+f"(c[j][3])
                    : "r"(__float_as_uint(a0)), "r"(__float_as_uint(a1)),
                      "r"(__float_as_uint(a2)), "r"(__float_as_uint(a3)),
                      "r"(__float_as_uint(b0)), "r"(__float_as_uint(b1)));
            }
        }

        // Epilogue: + P[L], relu, store (cols for this pass only)
#pragma unroll
        for (int half = 0; half < 2; ++half) {
            int eloc = wm * 16 + qr + half * 8;
            int ge = e0 + eloc;
            if (ge < E) {
                int L = Ls[eloc];
                const float2* prow = P2 + (size_t)L * 64;
                float2* orow = out2 + (size_t)ge * 64;
#pragma unroll
                for (int j = 0; j < 4; ++j) {
                    int col = h * 64 + wn * 32 + 8 * j + qc * 2;
                    float2 p = prow[col >> 1];
                    float2 v;
                    v.x = fmaxf(c[j][half * 2 + 0] + p.x, 0.f);
                    v.y = fmaxf(c[j][half * 2 + 1] + p.y, 0.f);
                    orow[col >> 1] = v;
                }
            }
        }
        __syncthreads();   // B buffer reused next pass
    }
}

// ---------------------------------------------------------------------------
// Global kernel: one block (128 thr) per graph; batch sorted -> binary search.
__global__ void global_kernel(const float* __restrict__ xnew,
                              const int* __restrict__ batch,
                              const float* __restrict__ glob,
                              const float* __restrict__ W_g,
                              const float* __restrict__ b_g,
                              float* __restrict__ gout, int nNodes)
{
    const int b = blockIdx.x;
    const int tid = threadIdx.x;  // 128 threads

    int lo = 0, hi = nNodes;
    while (lo < hi) { int mid = (lo + hi) >> 1; if (batch[mid] < b) lo = mid + 1; else hi = mid; }
    int s = lo;
    lo = s; hi = nNodes;
    while (lo < hi) { int mid = (lo + hi) >> 1; if (batch[mid] < b + 1) lo = mid + 1; else hi = mid; }
    int e2 = lo;

    float sum = 0.f;
    for (int row = s; row < e2; ++row) sum += xnew[(size_t)row * 128 + tid];

    __shared__ float mean_s[128];
    __shared__ float glob_s[64];
    float cnt = fmaxf((float)(e2 - s), 1.0f);
    mean_s[tid] = sum / cnt;
    if (tid < 64) glob_s[tid] = glob[b * 64 + tid];
    __syncthreads();

    if (tid < 64) {
        float acc = b_g[tid];
        for (int k = 0; k < 64; ++k)  acc = fmaf(glob_s[k], W_g[k * 64 + tid], acc);
        for (int k = 0; k < 128; ++k) acc = fmaf(mean_s[k], W_g[(64 + k) * 64 + tid], acc);
        gout[b * 64 + tid] = fmaxf(acc, 0.f);
    }
}

// ---------------------------------------------------------------------------
extern "C" void kernel_launch(void* const* d_in, const int* in_sizes, int n_in,
                              void* d_out, int out_size) {
    const float* x         = (const float*)d_in[0];
    const int*   eidx      = (const int*)d_in[1];
    const float* edge_attr = (const float*)d_in[2];
    const float* glob      = (const float*)d_in[3];
    const int*   batch     = (const int*)d_in[4];
    const float* W_e       = (const float*)d_in[5];
    const float* b_e       = (const float*)d_in[6];
    // d_in[7] = W_le, d_in[8] = b_le -- dead
    const float* W_n       = (const float*)d_in[9];
    const float* b_n       = (const float*)d_in[10];
    const float* W_n2      = (const float*)d_in[11];
    const float* b_n2      = (const float*)d_in[12];
    const float* W_g       = (const float*)d_in[13];
    const float* b_g       = (const float*)d_in[14];
    // d_in[15] = a -- dead

    const int N = in_sizes[0] / 128;
    const int E = in_sizes[1] / 2;
    const int B = in_sizes[3] / 64;

    float* xnew = (float*)d_out;               // [N,128]
    float* enew = xnew + (size_t)N * 128;      // [E,128]
    float* gnew = enew + (size_t)E * 128;      // [B,64]

    flags_zero_kernel<<<(N + 255) / 256, 256>>>(N);
    flags_set_kernel<<<(E + 255) / 256, 256>>>(eidx, E, N);
    precompute_kernel<<<129 + B + 64, 128>>>(W_n, b_n, W_n2, b_n2, glob, W_e, B);
    node_kernel<<<(N + 63) / 64, 256>>>(x, W_e, b_e, batch, xnew, N, B);
    edge_kernel<<<(E + 63) / 64, 256>>>(edge_attr, eidx, enew, E, N);
    global_kernel<<<B, 128>>>(xnew, batch, glob, W_g, b_g, gnew, N);
}

// round 12
// speedup vs baseline: 1.4906x; 1.1576x over previous
#include <cuda_runtime.h>
#include <cuda_fp16.h>

// ---------------------------------------------------------------------------
// GATv2 block — algebraically reduced; edge GEMM on tensor cores (fp16 mma
// m16n8k16, fp32 accumulate; fp16 mantissa == tf32 mantissa, both RN).
//
// Identities:
//   Sum_e alpha_e = 1 per destination node with >=1 incoming edge; agg gathers
//   nodes[R] (constant within a segment):
//     agg[n] = flag[n] * (x[n]@W_n + b_n)
//   x_new = relu( flag * (x@W_c + b_c) + G2[batch] )     (exact fp32)
//   e_new = relu( P[L] + edge_attr @ W_e[128:192] )       (fp16 mma + fp32 P)
//       P  = x@W_e[0:128] + b_e                           (exact fp32)
//   g_new = relu( [glob, segment_mean(x_new)] @ W_g + b_g )
// W_le, b_le, a are dead w.r.t. all outputs.
//
// R12: edge mainloop moved from tf32 m16n8k8 (192 LDS + 64 MMA / warp) to
// fp16 m16n8k16 (96 LDS + 32 MMA / warp); A converted in staging via
// cvt.rn.f16x2 (2 elem/instr), B pre-rounded once into d_Webh [n][k].
// ---------------------------------------------------------------------------

#define MAX_N 50000

__device__ __align__(16) float d_P[MAX_N * 128];   // x @ W_e_top + b_e
__device__ __align__(16) float d_Wc[128 * 128];    // W_n @ W_n2_top
__device__ __align__(16) float d_bc[128];          // b_n @ W_n2_top
__device__ __align__(16) float d_G2[64 * 128];     // glob @ W_n2_bot + b_n2
__device__ __align__(16) __half d_Webh[128 * 64];  // fp16 W_e[128:192], [n][k]
__device__ int d_flags[MAX_N];

__device__ __forceinline__ int clampi(int v, int lo, int hi) {
    return v < lo ? lo : (v > hi ? hi : v);
}

// ---------------------------------------------------------------------------
__global__ void flags_zero_kernel(int n) {
    int i = blockIdx.x * blockDim.x + threadIdx.x;
    if (i < n) d_flags[i] = 0;
}

__global__ void flags_set_kernel(const int* __restrict__ eidx, int E, int N) {
    int e = blockIdx.x * blockDim.x + threadIdx.x;
    if (e < E) {
        int r = eidx[E + e];  // edge_index[1][e] (destination)
        if ((unsigned)r < (unsigned)N) d_flags[r] = 1;
    }
}

// grid = 128 (W_c) + 1 (b_c) + B (G2) + 64 (Webh rows k=r); 128 threads
__global__ void precompute_kernel(const float* __restrict__ W_n,
                                  const float* __restrict__ b_n,
                                  const float* __restrict__ W_n2,
                                  const float* __restrict__ b_n2,
                                  const float* __restrict__ glob,
                                  const float* __restrict__ W_e, int nGraphs) {
    int blk = blockIdx.x;
    int j = threadIdx.x;  // 0..127
    if (blk < 128) {
        __shared__ float wr[128];
        wr[j] = W_n[blk * 128 + j];
        __syncthreads();
        float acc = 0.f;
#pragma unroll 8
        for (int k = 0; k < 128; ++k) acc = fmaf(wr[k], W_n2[k * 128 + j], acc);
        d_Wc[blk * 128 + j] = acc;
    } else if (blk == 128) {
        float acc = 0.f;
        for (int k = 0; k < 128; ++k) acc = fmaf(b_n[k], W_n2[k * 128 + j], acc);
        d_bc[j] = acc;
    } else if (blk < 129 + nGraphs) {
        int b = blk - 129;
        float acc = b_n2[j];
        for (int k = 0; k < 64; ++k)
            acc = fmaf(glob[b * 64 + k], W_n2[(128 + k) * 128 + j], acc);
        d_G2[b * 128 + j] = acc;
    } else {
        int r = blk - (129 + nGraphs);  // k index 0..63
        // [n][k] layout: d_Webh[n*64 + k] = fp16(W_e[(128+k)*128 + n])
        d_Webh[j * 64 + r] = __float2half_rn(W_e[(size_t)(128 + r) * 128 + j]);
    }
}

// ---------------------------------------------------------------------------
// Node kernel (exact fp32): per 64-node tile, (64x128)@(128x256) GEMM.
//   cols 0..127   -> P   -> d_P
//   cols 128..255 -> x_new epilogue (flag, +b_c, +G2[batch], relu)
__global__ __launch_bounds__(256, 2) void node_kernel(
    const float* __restrict__ x, const float* __restrict__ W_e,
    const float* __restrict__ b_e, const int* __restrict__ batch,
    float* __restrict__ xnew, int nNodes, int nGraphs)
{
    __shared__ __align__(16) float xs[64 * 128];   // 32 KB
    const int tid = threadIdx.x;
    const int n0 = blockIdx.x * 64;

    const float4* x4 = reinterpret_cast<const float4*>(x);
    float4* xs4w = reinterpret_cast<float4*>(xs);
    for (int idx = tid; idx < 64 * 32; idx += 256) {
        int node = idx >> 5, kk = idx & 31;
        int gn = n0 + node;
        xs4w[idx] = (gn < nNodes) ? x4[(size_t)gn * 32 + kk]
                                  : make_float4(0.f, 0.f, 0.f, 0.f);
    }
    __syncthreads();

    const int r = tid >> 6;
    const int c = tid & 63;

    const float4* wp = (c < 32)
        ? reinterpret_cast<const float4*>(W_e) + c
        : reinterpret_cast<const float4*>(d_Wc) + (c - 32);

    float acc[16][4];
#pragma unroll
    for (int i = 0; i < 16; ++i) {
        acc[i][0] = 0.f; acc[i][1] = 0.f; acc[i][2] = 0.f; acc[i][3] = 0.f;
    }

    const float4* xs4 = reinterpret_cast<const float4*>(xs);  // [64][32]

#pragma unroll 4
    for (int k4 = 0; k4 < 32; ++k4) {
        float4 w0 = wp[(k4 * 4 + 0) * 32];
        float4 w1 = wp[(k4 * 4 + 1) * 32];
        float4 w2 = wp[(k4 * 4 + 2) * 32];
        float4 w3 = wp[(k4 * 4 + 3) * 32];
#pragma unroll
        for (int i = 0; i < 16; ++i) {
            float4 xv = xs4[(r * 16 + i) * 32 + k4];
            acc[i][0] = fmaf(xv.x, w0.x, acc[i][0]);
            acc[i][1] = fmaf(xv.x, w0.y, acc[i][1]);
            acc[i][2] = fmaf(xv.x, w0.z, acc[i][2]);
            acc[i][3] = fmaf(xv.x, w0.w, acc[i][3]);
            acc[i][0] = fmaf(xv.y, w1.x, acc[i][0]);
            acc[i][1] = fmaf(xv.y, w1.y, acc[i][1]);
            acc[i][2] = fmaf(xv.y, w1.z, acc[i][2]);
            acc[i][3] = fmaf(xv.y, w1.w, acc[i][3]);
            acc[i][0] = fmaf(xv.z, w2.x, acc[i][0]);
            acc[i][1] = fmaf(xv.z, w2.y, acc[i][1]);
            acc[i][2] = fmaf(xv.z, w2.z, acc[i][2]);
            acc[i][3] = fmaf(xv.z, w2.w, acc[i][3]);
            acc[i][0] = fmaf(xv.w, w3.x, acc[i][0]);
            acc[i][1] = fmaf(xv.w, w3.y, acc[i][1]);
            acc[i][2] = fmaf(xv.w, w3.z, acc[i][2]);
            acc[i][3] = fmaf(xv.w, w3.w, acc[i][3]);
        }
    }

    if (c < 32) {
        const float4 bev = reinterpret_cast<const float4*>(b_e)[c];
        float4* P4 = reinterpret_cast<float4*>(d_P);
#pragma unroll
        for (int i = 0; i < 16; ++i) {
            int gn = n0 + r * 16 + i;
            if (gn < nNodes) {
                P4[(size_t)gn * 32 + c] =
                    make_float4(acc[i][0] + bev.x, acc[i][1] + bev.y,
                                acc[i][2] + bev.z, acc[i][3] + bev.w);
            }
        }
    } else {
        const int cc = c - 32;
        const float4 bcv = reinterpret_cast<const float4*>(d_bc)[cc];
        const float4* G24 = reinterpret_cast<const float4*>(d_G2);
        float4* out4 = reinterpret_cast<float4*>(xnew);
#pragma unroll
        for (int i = 0; i < 16; ++i) {
            int gn = n0 + r * 16 + i;
            if (gn < nNodes) {
                int fl = d_flags[gn];
                int b = clampi(batch[gn], 0, nGraphs - 1);
                float4 g2 = G24[b * 32 + cc];
                float4 v;
                v.x = (fl ? acc[i][0] + bcv.x : 0.f) + g2.x;
                v.y = (fl ? acc[i][1] + bcv.y : 0.f) + g2.y;
                v.z = (fl ? acc[i][2] + bcv.z : 0.f) + g2.z;
                v.w = (fl ? acc[i][3] + bcv.w : 0.f) + g2.w;
                v.x = fmaxf(v.x, 0.f); v.y = fmaxf(v.y, 0.f);
                v.z = fmaxf(v.z, 0.f); v.w = fmaxf(v.w, 0.f);
                out4[(size_t)gn * 32 + cc] = v;
            }
        }
    }
}

// ---------------------------------------------------------------------------
// Edge kernel (fp16 mma m16n8k16): e_new = relu(P[L] + edge_attr @ W_eb).
// Block = 64 edges x 128 cols, 256 threads (8 warps: 4 in m x 2 in n).
// Two n-passes of 64 cols; A (fp16, stride 72 halves) loaded+converted once;
// B (fp16 [n][k], stride 72 halves) staged per pass from d_Webh.
// Fragment LDS word-banks = 4*qr+qc, conflict-free. fp32 epilogue: +P, relu.
__global__ __launch_bounds__(256) void edge_kernel(
    const float* __restrict__ edge_attr, const int* __restrict__ eidx,
    float* __restrict__ enew, int E, int nNodes)
{
    __shared__ __align__(16) __half es[64 * 72];   // A: 9216 B
    __shared__ __align__(16) __half Ws[64 * 72];   // B: 9216 B
    __shared__ int Ls[64];

    const int tid = threadIdx.x;
    const int e0 = blockIdx.x * 64;

    if (tid < 64) {
        int ge = e0 + tid;
        Ls[tid] = (ge < E) ? clampi(eidx[ge], 0, nNodes - 1) : 0;
    }

    // A tile: 64 edges x 64 k, fp32 -> fp16 RN during staging
    const float4* ea4 = reinterpret_cast<const float4*>(edge_attr);
#pragma unroll
    for (int it = 0; it < 4; ++it) {
        int idx = tid + it * 256;            // 0..1023
        int e = idx >> 4, kk = idx & 15;     // kk = 4-float chunk (16 per row)
        int ge = e0 + e;
        float4 v = (ge < E) ? ea4[(size_t)ge * 16 + kk]
                            : make_float4(0.f, 0.f, 0.f, 0.f);
        __half2* dst = reinterpret_cast<__half2*>(es + e * 72 + kk * 4);
        dst[0] = __floats2half2_rn(v.x, v.y);
        dst[1] = __floats2half2_rn(v.z, v.w);
    }

    const int warp = tid >> 5;
    const int lane = tid & 31;
    const int wm = warp & 3;      // m group: rows [16*wm, 16*wm+16)
    const int wn = warp >> 2;     // n group: pass-local cols [32*wn, +32)
    const int qr = lane >> 2;     // 0..7
    const int qc = lane & 3;      // 0..3

    // uint-indexed views (1 uint = 2 halves; row stride = 36 uints)
    const unsigned* esu = reinterpret_cast<const unsigned*>(es);
    const unsigned* Wsu = reinterpret_cast<const unsigned*>(Ws);
    const int r0u = (wm * 16 + qr) * 36;
    const int r1u = r0u + 8 * 36;

    const float2* P2 = reinterpret_cast<const float2*>(d_P);
    float2* out2 = reinterpret_cast<float2*>(enew);
    const float4* Wh4 = reinterpret_cast<const float4*>(d_Webh);  // 8 f4/row

#pragma unroll
    for (int h = 0; h < 2; ++h) {
        // B half: 64 n-rows (cols [64h,64h+64)) x 64 k halves, stride 72
#pragma unroll
        for (int it = 0; it < 2; ++it) {
            int idx = tid + it * 256;        // 0..511
            int n = idx >> 3, c8 = idx & 7;  // c8 = 8-half chunk
            float4 v = Wh4[(size_t)(h * 64 + n) * 8 + c8];
            *reinterpret_cast<float4*>(Ws + n * 72 + c8 * 8) = v;
        }
        __syncthreads();

        float c[4][4];
#pragma unroll
        for (int j = 0; j < 4; ++j) {
            c[j][0] = 0.f; c[j][1] = 0.f; c[j][2] = 0.f; c[j][3] = 0.f;
        }

#pragma unroll
        for (int s = 0; s < 4; ++s) {        // k16 steps
            unsigned a0 = esu[r0u + 8 * s + qc];
            unsigned a1 = esu[r1u + 8 * s + qc];
            unsigned a2 = esu[r0u + 8 * s + qc + 4];
            unsigned a3 = esu[r1u + 8 * s + qc + 4];
#pragma unroll
            for (int j = 0; j < 4; ++j) {
                int nrow = (wn * 32 + 8 * j + qr) * 36;
                unsigned b0 = Wsu[nrow + 8 * s + qc];
                unsigned b1 = Wsu[nrow + 8 * s + qc + 4];
                asm volatile(
                    "mma.sync.aligned.m16n8k16.row.col.f32.f16.f16.f32 "
                    "{%0,%1,%2,%3}, {%4,%5,%6,%7}, {%8,%9}, {%0,%1,%2,%3};"
                    : "+f"(c[j][0]), "+f"(c[j][1]), "+f"(c[j][2]), "+f"(c[j][3])
                    : "r"(a0), "r"(a1), "r"(a2), "r"(a3),
                      "r"(b0), "r"(b1));
            }
        }

        // Epilogue: + P[L], relu, store (cols for this pass only)
#pragma unroll
        for (int half = 0; half < 2; ++half) {
            int eloc = wm * 16 + qr + half * 8;
            int ge = e0 + eloc;
            if (ge < E) {
                int L = Ls[eloc];
                const float2* prow = P2 + (size_t)L * 64;
                float2* orow = out2 + (size_t)ge * 64;
#pragma unroll
                for (int j = 0; j < 4; ++j) {
                    int col = h * 64 + wn * 32 + 8 * j + qc * 2;
                    float2 p = prow[col >> 1];
                    float2 v;
                    v.x = fmaxf(c[j][half * 2 + 0] + p.x, 0.f);
                    v.y = fmaxf(c[j][half * 2 + 1] + p.y, 0.f);
                    orow[col >> 1] = v;
                }
            }
        }
        __syncthreads();   // B buffer reused next pass
    }
}

// ---------------------------------------------------------------------------
// Global kernel: one block (128 thr) per graph; batch sorted -> binary search.
__global__ void global_kernel(const float* __restrict__ xnew,
                              const int* __restrict__ batch,
                              const float* __restrict__ glob,
                              const float* __restrict__ W_g,
                              const float* __restrict__ b_g,
                              float* __restrict__ gout, int nNodes)
{
    const int b = blockIdx.x;
    const int tid = threadIdx.x;  // 128 threads

    int lo = 0, hi = nNodes;
    while (lo < hi) { int mid = (lo + hi) >> 1; if (batch[mid] < b) lo = mid + 1; else hi = mid; }
    int s = lo;
    lo = s; hi = nNodes;
    while (lo < hi) { int mid = (lo + hi) >> 1; if (batch[mid] < b + 1) lo = mid + 1; else hi = mid; }
    int e2 = lo;

    float sum = 0.f;
    for (int row = s; row < e2; ++row) sum += xnew[(size_t)row * 128 + tid];

    __shared__ float mean_s[128];
    __shared__ float glob_s[64];
    float cnt = fmaxf((float)(e2 - s), 1.0f);
    mean_s[tid] = sum / cnt;
    if (tid < 64) glob_s[tid] = glob[b * 64 + tid];
    __syncthreads();

    if (tid < 64) {
        float acc = b_g[tid];
        for (int k = 0; k < 64; ++k)  acc = fmaf(glob_s[k], W_g[k * 64 + tid], acc);
        for (int k = 0; k < 128; ++k) acc = fmaf(mean_s[k], W_g[(64 + k) * 64 + tid], acc);
        gout[b * 64 + tid] = fmaxf(acc, 0.f);
    }
}

// ---------------------------------------------------------------------------
extern "C" void kernel_launch(void* const* d_in, const int* in_sizes, int n_in,
                              void* d_out, int out_size) {
    const float* x         = (const float*)d_in[0];
    const int*   eidx      = (const int*)d_in[1];
    const float* edge_attr = (const float*)d_in[2];
    const float* glob      = (const float*)d_in[3];
    const int*   batch     = (const int*)d_in[4];
    const float* W_e       = (const float*)d_in[5];
    const float* b_e       = (const float*)d_in[6];
    // d_in[7] = W_le, d_in[8] = b_le -- dead
    const float* W_n       = (const float*)d_in[9];
    const float* b_n       = (const float*)d_in[10];
    const float* W_n2      = (const float*)d_in[11];
    const float* b_n2      = (const float*)d_in[12];
    const float* W_g       = (const float*)d_in[13];
    const float* b_g       = (const float*)d_in[14];
    // d_in[15] = a -- dead

    const int N = in_sizes[0] / 128;
    const int E = in_sizes[1] / 2;
    const int B = in_sizes[3] / 64;

    float* xnew = (float*)d_out;               // [N,128]
    float* enew = xnew + (size_t)N * 128;      // [E,128]
    float* gnew = enew + (size_t)E * 128;      // [B,64]

    flags_zero_kernel<<<(N + 255) / 256, 256>>>(N);
    flags_set_kernel<<<(E + 255) / 256, 256>>>(eidx, E, N);
    precompute_kernel<<<129 + B + 64, 128>>>(W_n, b_n, W_n2, b_n2, glob, W_e, B);
    node_kernel<<<(N + 63) / 64, 256>>>(x, W_e, b_e, batch, xnew, N, B);
    edge_kernel<<<(E + 63) / 64, 256>>>(edge_attr, eidx, enew, E, N);
    global_kernel<<<B, 128>>>(xnew, batch, glob, W_g, b_g, gnew, N);
}